// round 1
// baseline (speedup 1.0000x reference)
#include <cuda_runtime.h>

#define Bsz 16
#define Cch 512
#define Nsp 1024      // H*W = 32*32
#define Gg  32
#define CPG 16        // channels per group
#define EPSf 1e-6f
#define SCALE 0.044194173824159216f  // 512^-0.5

// ---------------- scratch (static device globals; no runtime allocation) ----
__device__ float g_hn[Bsz * Cch * Nsp];
__device__ float g_q [Bsz * Cch * Nsp];
__device__ float g_k [Bsz * Cch * Nsp];
__device__ float g_v [Bsz * Cch * Nsp];
__device__ float g_o [Bsz * Cch * Nsp];
__device__ float g_attn[(size_t)Bsz * Nsp * Nsp];

// ---------------- GroupNorm: one block per (b, g) ---------------------------
__global__ void __launch_bounds__(256) gn_kernel(const float* __restrict__ x,
                                                 const float* __restrict__ gamma,
                                                 const float* __restrict__ beta) {
    int b = blockIdx.x >> 5;
    int g = blockIdx.x & 31;
    const float* xp = x + (size_t)(b * Gg + g) * CPG * Nsp;
    float* hp = g_hn + (size_t)(b * Gg + g) * CPG * Nsp;

    float s = 0.f, ss = 0.f;
    for (int i = threadIdx.x; i < CPG * Nsp; i += 256) {
        float v = xp[i];
        s += v; ss += v * v;
    }
    __shared__ float shs[8], shss[8], stats[2];
    for (int o = 16; o > 0; o >>= 1) {
        s  += __shfl_xor_sync(~0u, s,  o);
        ss += __shfl_xor_sync(~0u, ss, o);
    }
    int w = threadIdx.x >> 5, l = threadIdx.x & 31;
    if (l == 0) { shs[w] = s; shss[w] = ss; }
    __syncthreads();
    if (threadIdx.x < 8) {
        s = shs[threadIdx.x]; ss = shss[threadIdx.x];
        for (int o = 4; o > 0; o >>= 1) {
            s  += __shfl_xor_sync(0xff, s,  o);
            ss += __shfl_xor_sync(0xff, ss, o);
        }
        if (threadIdx.x == 0) {
            float mu  = s * (1.f / (CPG * Nsp));
            float var = ss * (1.f / (CPG * Nsp)) - mu * mu;
            stats[0] = mu;
            stats[1] = rsqrtf(var + EPSf);
        }
    }
    __syncthreads();
    float mu = stats[0], inv = stats[1];
    for (int i = threadIdx.x; i < CPG * Nsp; i += 256) {
        int c = g * CPG + (i >> 10);           // i / Nsp
        hp[i] = (xp[i] - mu) * inv * gamma[c] + beta[c];
    }
}

// ---------------- projection GEMM: out[b,d,n] = sum_c W[c,d]*in[b,c,n] (+bias)(+x)
// MODE 0/1/2: g_hn -> g_q/g_k/g_v.  MODE 3: g_o -> d_out, epilogue adds bias + x.
// Tile: 64x64 output, BK=16, 256 threads, 4x4 micro-tile.
template<int MODE>
__global__ void __launch_bounds__(256) proj_kernel(const float* __restrict__ Wm,
                                                   const float* __restrict__ bias,
                                                   const float* __restrict__ xres,
                                                   float* __restrict__ dout) {
    const float* in = (MODE == 3) ? g_o : g_hn;
    float* out = (MODE == 0) ? g_q : (MODE == 1) ? g_k : (MODE == 2) ? g_v : dout;

    int b  = blockIdx.z;
    int m0 = blockIdx.y * 64;      // output channel d
    int n0 = blockIdx.x * 64;      // spatial
    __shared__ float As[16][64];   // W[c][d] tile
    __shared__ float Bs[16][64];   // in[c][n] tile
    const float* inb = in + (size_t)b * Cch * Nsp;

    int tid = threadIdx.x;
    int tx = tid & 15, ty = tid >> 4;
    float acc[4][4] = {};

    for (int k0 = 0; k0 < Cch; k0 += 16) {
        #pragma unroll
        for (int t = 0; t < 4; t++) {
            int i  = tid + t * 256;
            int kk = i >> 6, col = i & 63;
            As[kk][col] = Wm[(k0 + kk) * Cch + m0 + col];
            Bs[kk][col] = inb[(k0 + kk) * Nsp + n0 + col];
        }
        __syncthreads();
        #pragma unroll
        for (int kk = 0; kk < 16; kk++) {
            float4 a  = *(const float4*)&As[kk][ty * 4];
            float4 bb = *(const float4*)&Bs[kk][tx * 4];
            float ar[4] = {a.x, a.y, a.z, a.w};
            float br[4] = {bb.x, bb.y, bb.z, bb.w};
            #pragma unroll
            for (int i = 0; i < 4; i++)
                #pragma unroll
                for (int j = 0; j < 4; j++)
                    acc[i][j] += ar[i] * br[j];
        }
        __syncthreads();
    }

    float* ob = out + (size_t)b * Cch * Nsp;
    const float* xb = (MODE == 3) ? (xres + (size_t)b * Cch * Nsp) : nullptr;
    #pragma unroll
    for (int i = 0; i < 4; i++) {
        int m = m0 + ty * 4 + i;
        float bi = bias[m];
        #pragma unroll
        for (int j = 0; j < 4; j++) {
            int idx = m * Nsp + n0 + tx * 4 + j;
            float r = acc[i][j] + bi;
            if (MODE == 3) r += xb[idx];
            ob[idx] = r;
        }
    }
}

// ---------------- scores: attn[b,n,m] = SCALE * sum_c q[b,c,n]*k[b,c,m] ------
__global__ void __launch_bounds__(256) scores_kernel() {
    int b  = blockIdx.z;
    int i0 = blockIdx.y * 64;  // query position n
    int j0 = blockIdx.x * 64;  // key position m
    __shared__ float As[16][64];
    __shared__ float Bs[16][64];
    const float* qb = g_q + (size_t)b * Cch * Nsp;
    const float* kb = g_k + (size_t)b * Cch * Nsp;

    int tid = threadIdx.x;
    int tx = tid & 15, ty = tid >> 4;
    float acc[4][4] = {};

    for (int k0 = 0; k0 < Cch; k0 += 16) {
        #pragma unroll
        for (int t = 0; t < 4; t++) {
            int i  = tid + t * 256;
            int kk = i >> 6, col = i & 63;
            As[kk][col] = qb[(k0 + kk) * Nsp + i0 + col];
            Bs[kk][col] = kb[(k0 + kk) * Nsp + j0 + col];
        }
        __syncthreads();
        #pragma unroll
        for (int kk = 0; kk < 16; kk++) {
            float4 a  = *(const float4*)&As[kk][ty * 4];
            float4 bb = *(const float4*)&Bs[kk][tx * 4];
            float ar[4] = {a.x, a.y, a.z, a.w};
            float br[4] = {bb.x, bb.y, bb.z, bb.w};
            #pragma unroll
            for (int i = 0; i < 4; i++)
                #pragma unroll
                for (int j = 0; j < 4; j++)
                    acc[i][j] += ar[i] * br[j];
        }
        __syncthreads();
    }

    float* pb = g_attn + (size_t)b * Nsp * Nsp;
    #pragma unroll
    for (int i = 0; i < 4; i++)
        #pragma unroll
        for (int j = 0; j < 4; j++)
            pb[(size_t)(i0 + ty * 4 + i) * Nsp + j0 + tx * 4 + j] = acc[i][j] * SCALE;
}

// ---------------- row softmax over 1024 keys --------------------------------
__global__ void __launch_bounds__(256) softmax_kernel() {
    float* p = g_attn + (size_t)blockIdx.x * Nsp;
    int t = threadIdx.x;
    float v0 = p[t], v1 = p[t + 256], v2 = p[t + 512], v3 = p[t + 768];

    __shared__ float sh[8], sh2[8], bc[2];
    float mx = fmaxf(fmaxf(v0, v1), fmaxf(v2, v3));
    for (int o = 16; o > 0; o >>= 1) mx = fmaxf(mx, __shfl_xor_sync(~0u, mx, o));
    if ((t & 31) == 0) sh[t >> 5] = mx;
    __syncthreads();
    if (t < 8) {
        float m = sh[t];
        for (int o = 4; o > 0; o >>= 1) m = fmaxf(m, __shfl_xor_sync(0xff, m, o));
        if (t == 0) bc[0] = m;
    }
    __syncthreads();
    mx = bc[0];

    v0 = __expf(v0 - mx); v1 = __expf(v1 - mx);
    v2 = __expf(v2 - mx); v3 = __expf(v3 - mx);
    float s = v0 + v1 + v2 + v3;
    for (int o = 16; o > 0; o >>= 1) s += __shfl_xor_sync(~0u, s, o);
    if ((t & 31) == 0) sh2[t >> 5] = s;
    __syncthreads();
    if (t < 8) {
        float m = sh2[t];
        for (int o = 4; o > 0; o >>= 1) m += __shfl_xor_sync(0xff, m, o);
        if (t == 0) bc[1] = 1.f / m;
    }
    __syncthreads();
    float inv = bc[1];
    p[t] = v0 * inv; p[t + 256] = v1 * inv; p[t + 512] = v2 * inv; p[t + 768] = v3 * inv;
}

// ---------------- o[b,c,n] = sum_m attn[b,n,m] * v[b,c,m] -------------------
// K = m (1024). Both operands are contiguous along m -> load coalesced, store
// transposed into [BK][tile+4]-padded smem so fragments are float4-readable.
__global__ void __launch_bounds__(256) av_kernel() {
    int b  = blockIdx.z;
    int c0 = blockIdx.y * 64;
    int n0 = blockIdx.x * 64;
    __shared__ float Vs[16][68];
    __shared__ float Ps[16][68];
    const float* vb = g_v + (size_t)b * Cch * Nsp;
    const float* pb = g_attn + (size_t)b * Nsp * Nsp;

    int tid = threadIdx.x;
    int tx = tid & 15, ty = tid >> 4;
    float acc[4][4] = {};

    for (int m0 = 0; m0 < Nsp; m0 += 16) {
        #pragma unroll
        for (int t = 0; t < 4; t++) {
            int i  = tid + t * 256;
            int r  = i >> 4;     // tile row (c or n), 0..63
            int kk = i & 15;     // k index, contiguous in gmem
            Vs[kk][r] = vb[(c0 + r) * Nsp + m0 + kk];
            Ps[kk][r] = pb[(size_t)(n0 + r) * Nsp + m0 + kk];
        }
        __syncthreads();
        #pragma unroll
        for (int kk = 0; kk < 16; kk++) {
            float4 a  = *(const float4*)&Vs[kk][ty * 4];
            float4 bb = *(const float4*)&Ps[kk][tx * 4];
            float ar[4] = {a.x, a.y, a.z, a.w};
            float br[4] = {bb.x, bb.y, bb.z, bb.w};
            #pragma unroll
            for (int i = 0; i < 4; i++)
                #pragma unroll
                for (int j = 0; j < 4; j++)
                    acc[i][j] += ar[i] * br[j];
        }
        __syncthreads();
    }

    float* ob = g_o + (size_t)b * Cch * Nsp;
    #pragma unroll
    for (int i = 0; i < 4; i++)
        #pragma unroll
        for (int j = 0; j < 4; j++)
            ob[(c0 + ty * 4 + i) * Nsp + n0 + tx * 4 + j] = acc[i][j];
}

// ---------------- launch ----------------------------------------------------
extern "C" void kernel_launch(void* const* d_in, const int* in_sizes, int n_in,
                              void* d_out, int out_size) {
    const float* x     = (const float*)d_in[0];
    const float* gamma = (const float*)d_in[1];
    const float* beta  = (const float*)d_in[2];
    const float* W0 = (const float*)d_in[3];  const float* b0 = (const float*)d_in[4];
    const float* W1 = (const float*)d_in[5];  const float* b1 = (const float*)d_in[6];
    const float* W2 = (const float*)d_in[7];  const float* b2 = (const float*)d_in[8];
    const float* W3 = (const float*)d_in[9];  const float* b3 = (const float*)d_in[10];
    float* out = (float*)d_out;

    gn_kernel<<<Bsz * Gg, 256>>>(x, gamma, beta);

    dim3 gp(Nsp / 64, Cch / 64, Bsz);          // (16, 8, 16)
    proj_kernel<0><<<gp, 256>>>(W0, b0, nullptr, nullptr);
    proj_kernel<1><<<gp, 256>>>(W1, b1, nullptr, nullptr);
    proj_kernel<2><<<gp, 256>>>(W2, b2, nullptr, nullptr);

    dim3 gs(Nsp / 64, Nsp / 64, Bsz);          // (16, 16, 16)
    scores_kernel<<<gs, 256>>>();

    softmax_kernel<<<Bsz * Nsp, 256>>>();

    av_kernel<<<gp, 256>>>();

    proj_kernel<3><<<gp, 256>>>(W3, b3, x, out);
}

// round 3
// speedup vs baseline: 5.1531x; 5.1531x over previous
#include <cuda_runtime.h>
#include <cuda_fp16.h>
#include <cstdint>

#define Bsz 16
#define Cch 512
#define Nsp 1024
#define Gg  32
#define CPG 16
#define EPSf 1e-6f
#define SCALE 0.044194173824159216f   // 512^-0.5

// ---------------- scratch ----------------------------------------------------
__device__ __half g_hn[Bsz * Nsp * Cch];             // [b][n][c]
__device__ __half g_q [Bsz * Nsp * Cch];             // [b][n][d]  (pre-scaled)
__device__ __half g_k [Bsz * Nsp * Cch];             // [b][n][d]
__device__ __half g_v [Bsz * Cch * Nsp];             // [b][d][n]
__device__ __half g_o [Bsz * Nsp * Cch];             // [b][n][c]
__device__ float  g_attn [(size_t)Bsz * Nsp * Nsp];  // fp32 scores
__device__ __half g_attnh[(size_t)Bsz * Nsp * Nsp];  // fp16 probs
__device__ __half g_wt[4 * Cch * Cch];               // Wt[w][d][c] = W[c][d]
__device__ float  g_mu[Bsz * Gg];
__device__ float  g_iv[Bsz * Gg];

// ---------------- PTX helpers (baseline ISA only: sm_80-level) ---------------
__device__ __forceinline__ uint32_t smem_u32(const void* p) {
    uint32_t a;
    asm("{ .reg .u64 t; cvta.to.shared.u64 t, %1; cvt.u32.u64 %0, t; }" : "=r"(a) : "l"(p));
    return a;
}
#define CP16(saddr, gptr) \
    asm volatile("cp.async.cg.shared.global [%0], [%1], 16;" :: "r"(saddr), "l"(gptr))
#define CPCOMMIT() asm volatile("cp.async.commit_group;")
#define CPWAIT0()  asm volatile("cp.async.wait_group 0;")
#define LDSM4(r, a) \
    asm volatile("ldmatrix.sync.aligned.m8n8.x4.shared.b16 {%0,%1,%2,%3}, [%4];" \
        : "=r"((r)[0]), "=r"((r)[1]), "=r"((r)[2]), "=r"((r)[3]) : "r"(a))
#define MMA16816(d, a, b0, b1) \
    asm volatile("mma.sync.aligned.m16n8k16.row.col.f32.f16.f16.f32 " \
        "{%0,%1,%2,%3},{%4,%5,%6,%7},{%8,%9},{%0,%1,%2,%3};" \
        : "+f"((d)[0]), "+f"((d)[1]), "+f"((d)[2]), "+f"((d)[3]) \
        : "r"((a)[0]), "r"((a)[1]), "r"((a)[2]), "r"((a)[3]), "r"(b0), "r"(b1))

// ---------------- GN stats ---------------------------------------------------
__global__ void __launch_bounds__(256) gn_stats(const float* __restrict__ x) {
    int b = blockIdx.x >> 5, g = blockIdx.x & 31;
    const float* xp = x + (size_t)(b * Cch + g * CPG) * Nsp;
    float s = 0.f, ss = 0.f;
    for (int i = threadIdx.x; i < CPG * Nsp; i += 256) {
        float v = xp[i]; s += v; ss += v * v;
    }
    __shared__ float shs[8], shss[8];
    for (int o = 16; o > 0; o >>= 1) { s += __shfl_xor_sync(~0u, s, o); ss += __shfl_xor_sync(~0u, ss, o); }
    if ((threadIdx.x & 31) == 0) { shs[threadIdx.x >> 5] = s; shss[threadIdx.x >> 5] = ss; }
    __syncthreads();
    if (threadIdx.x < 8) {
        s = shs[threadIdx.x]; ss = shss[threadIdx.x];
        for (int o = 4; o > 0; o >>= 1) { s += __shfl_xor_sync(0xff, s, o); ss += __shfl_xor_sync(0xff, ss, o); }
        if (threadIdx.x == 0) {
            float mu = s * (1.f / (CPG * Nsp));
            float var = ss * (1.f / (CPG * Nsp)) - mu * mu;
            g_mu[blockIdx.x] = mu;
            g_iv[blockIdx.x] = rsqrtf(var + EPSf);
        }
    }
}

// ---------------- GN apply + transpose: x[c][n] fp32 -> hn[n][c] fp16 --------
__global__ void __launch_bounds__(256) gn_apply_t(const float* __restrict__ x,
                                                  const float* __restrict__ gamma,
                                                  const float* __restrict__ beta) {
    __shared__ float t[32][33];
    int b = blockIdx.z, c0 = blockIdx.y * 32, n0 = blockIdx.x * 32;
    int tx = threadIdx.x & 31, ty = threadIdx.x >> 5;
    const float* xb = x + (size_t)b * Cch * Nsp;
    #pragma unroll
    for (int i = 0; i < 4; i++) {
        int c = c0 + ty + i * 8;
        float mu = g_mu[b * Gg + (c >> 4)], iv = g_iv[b * Gg + (c >> 4)];
        float v = xb[(size_t)c * Nsp + n0 + tx];
        t[ty + i * 8][tx] = (v - mu) * iv * gamma[c] + beta[c];
    }
    __syncthreads();
    __half* hb = g_hn + (size_t)b * Nsp * Cch;
    #pragma unroll
    for (int i = 0; i < 4; i++)
        hb[(size_t)(n0 + ty + i * 8) * Cch + c0 + tx] = __float2half_rn(t[tx][ty + i * 8]);
}

// ---------------- weight transpose: Wt[d][c] = fp16(W[c][d]) -----------------
__global__ void __launch_bounds__(256) wt_kernel(const float* __restrict__ W0, const float* __restrict__ W1,
                                                 const float* __restrict__ W2, const float* __restrict__ W3) {
    __shared__ float t[32][33];
    int w = blockIdx.z;
    const float* src = (w == 0) ? W0 : (w == 1) ? W1 : (w == 2) ? W2 : W3;
    __half* dst = g_wt + (size_t)w * Cch * Cch;
    int c0 = blockIdx.y * 32, d0 = blockIdx.x * 32;
    int tx = threadIdx.x & 31, ty = threadIdx.x >> 5;
    #pragma unroll
    for (int i = 0; i < 4; i++)
        t[ty + i * 8][tx] = src[(size_t)(c0 + ty + i * 8) * Cch + d0 + tx];
    __syncthreads();
    #pragma unroll
    for (int i = 0; i < 4; i++)
        dst[(size_t)(d0 + ty + i * 8) * Cch + c0 + tx] = __float2half_rn(t[tx][ty + i * 8]);
}

// ---------------- mma.sync GEMM: D[m][n'] = sum_k A[m][k]*B[n'][k] -----------
// CTA 128x128, BK=64 halves (128B rows, xor-swizzled), 8 warps 32x64 each.
struct GArgs {
    const __half* A; const __half* B; void* D;
    const float* bias; const float* res;
    long long sA, sB, sD;
    int lda, ldb, ldd, K;
    float alpha;
};

#define M_SCORES 0   // fp32 raw
#define M_QK     1   // fp16, alpha*(v + bias[col])
#define M_V      2   // fp16, v + bias[row]
#define M_AV     3   // fp16 raw
#define M_FINAL  4   // fp32, v + bias[row] + res

template<int MODE>
__global__ void __launch_bounds__(256) gemm_mma(const GArgs p) {
    extern __shared__ char smem[];
    const uint32_t sb = smem_u32(smem);
    const int tid = threadIdx.x, lane = tid & 31, wid = tid >> 5;
    const int wm = wid & 3, wn = wid >> 2;
    const int bz = blockIdx.z;
    const int M0 = blockIdx.y * 128, N0 = blockIdx.x * 128;

    // gmem->smem loader mapping: thread -> (row, 4 chunks of 16B)
    const int lr  = tid >> 1;
    const int lcb = (tid & 1) * 4;
    const __half* Ag = p.A + (long long)bz * p.sA + (long long)(M0 + lr) * p.lda;
    const __half* Bg = p.B + (long long)bz * p.sB + (long long)(N0 + lr) * p.ldb;
    const uint32_t rsw = (uint32_t)(lr & 7);
    const uint32_t sArow = sb + lr * 128;
    const uint32_t sBrow = sb + 16384 + lr * 128;

    float acc[2][8][4];
    #pragma unroll
    for (int i = 0; i < 2; i++)
        #pragma unroll
        for (int j = 0; j < 8; j++)
            #pragma unroll
            for (int q = 0; q < 4; q++) acc[i][j][q] = 0.f;

    const int S = p.K >> 6;

    // prefetch stage 0 into buf 0
    #pragma unroll
    for (int i = 0; i < 4; i++) {
        int c = lcb + i;
        uint32_t sw = ((uint32_t)c ^ rsw) << 4;
        CP16(sArow + sw, Ag + c * 8);
        CP16(sBrow + sw, Bg + c * 8);
    }
    CPCOMMIT();

    for (int s = 0; s < S; s++) {
        CPWAIT0();
        __syncthreads();
        if (s + 1 < S) {
            int buf = (s + 1) & 1;
            const __half* ga = Ag + (s + 1) * 64;
            const __half* gb = Bg + (s + 1) * 64;
            uint32_t oA = sArow + buf * 32768;
            uint32_t oB = sBrow + buf * 32768;
            #pragma unroll
            for (int i = 0; i < 4; i++) {
                int c = lcb + i;
                uint32_t sw = ((uint32_t)c ^ rsw) << 4;
                CP16(oA + sw, ga + c * 8);
                CP16(oB + sw, gb + c * 8);
            }
            CPCOMMIT();
        }
        uint32_t A0 = sb + (s & 1) * 32768;
        uint32_t B0 = A0 + 16384;
        #pragma unroll
        for (int ks = 0; ks < 4; ks++) {
            uint32_t afr[2][4];
            #pragma unroll
            for (int mt = 0; mt < 2; mt++) {
                int row = wm * 32 + mt * 16 + (lane & 15);
                int ch  = ks * 2 + (lane >> 4);
                LDSM4(afr[mt], A0 + row * 128 + (((uint32_t)ch ^ (uint32_t)(row & 7)) << 4));
            }
            uint32_t bfr[4][4];
            #pragma unroll
            for (int pp = 0; pp < 4; pp++) {
                int row = wn * 64 + pp * 16 + ((lane >> 4) << 3) + (lane & 7);
                int ch  = ks * 2 + ((lane >> 3) & 1);
                LDSM4(bfr[pp], B0 + row * 128 + (((uint32_t)ch ^ (uint32_t)(row & 7)) << 4));
            }
            #pragma unroll
            for (int mt = 0; mt < 2; mt++)
                #pragma unroll
                for (int nt = 0; nt < 8; nt++)
                    MMA16816(acc[mt][nt], afr[mt], bfr[nt >> 1][(nt & 1) * 2], bfr[nt >> 1][(nt & 1) * 2 + 1]);
        }
        __syncthreads();
    }

    // ------------- epilogue -------------
    const int mbase = M0 + wm * 32 + (lane >> 2);
    const int nbase = N0 + wn * 64 + (lane & 3) * 2;
    #pragma unroll
    for (int mt = 0; mt < 2; mt++) {
        int r0 = mbase + mt * 16, r1 = r0 + 8;
        float bi0 = 0.f, bi1 = 0.f;
        if (MODE == M_V || MODE == M_FINAL) { bi0 = __ldg(&p.bias[r0]); bi1 = __ldg(&p.bias[r1]); }
        #pragma unroll
        for (int nt = 0; nt < 8; nt++) {
            int cc = nbase + nt * 8;
            float v0 = acc[mt][nt][0], v1 = acc[mt][nt][1];
            float v2 = acc[mt][nt][2], v3 = acc[mt][nt][3];
            if (MODE == M_SCORES) {
                float* Dp = (float*)p.D + (long long)bz * p.sD;
                *(float2*)(Dp + (size_t)r0 * p.ldd + cc) = make_float2(v0, v1);
                *(float2*)(Dp + (size_t)r1 * p.ldd + cc) = make_float2(v2, v3);
            } else if (MODE == M_QK) {
                __half* Dh = (__half*)p.D + (long long)bz * p.sD;
                float c0 = __ldg(&p.bias[cc]), c1 = __ldg(&p.bias[cc + 1]);
                *(__half2*)(Dh + (size_t)r0 * p.ldd + cc) =
                    __floats2half2_rn(p.alpha * (v0 + c0), p.alpha * (v1 + c1));
                *(__half2*)(Dh + (size_t)r1 * p.ldd + cc) =
                    __floats2half2_rn(p.alpha * (v2 + c0), p.alpha * (v3 + c1));
            } else if (MODE == M_V) {
                __half* Dh = (__half*)p.D + (long long)bz * p.sD;
                *(__half2*)(Dh + (size_t)r0 * p.ldd + cc) = __floats2half2_rn(v0 + bi0, v1 + bi0);
                *(__half2*)(Dh + (size_t)r1 * p.ldd + cc) = __floats2half2_rn(v2 + bi1, v3 + bi1);
            } else if (MODE == M_AV) {
                __half* Dh = (__half*)p.D + (long long)bz * p.sD;
                *(__half2*)(Dh + (size_t)r0 * p.ldd + cc) = __floats2half2_rn(v0, v1);
                *(__half2*)(Dh + (size_t)r1 * p.ldd + cc) = __floats2half2_rn(v2, v3);
            } else {
                float* Dp = (float*)p.D + (long long)bz * p.sD;
                const float* Rp = p.res + (long long)bz * p.sD;
                float2 x0 = *(const float2*)(Rp + (size_t)r0 * p.ldd + cc);
                float2 x1 = *(const float2*)(Rp + (size_t)r1 * p.ldd + cc);
                *(float2*)(Dp + (size_t)r0 * p.ldd + cc) = make_float2(v0 + bi0 + x0.x, v1 + bi0 + x0.y);
                *(float2*)(Dp + (size_t)r1 * p.ldd + cc) = make_float2(v2 + bi1 + x1.x, v3 + bi1 + x1.y);
            }
        }
    }
}

// ---------------- row softmax: fp32 scores -> fp16 probs ---------------------
__global__ void __launch_bounds__(256) softmax_kernel() {
    const float* pr = g_attn + (size_t)blockIdx.x * Nsp;
    __half* ph = g_attnh + (size_t)blockIdx.x * Nsp;
    int t = threadIdx.x;
    float v0 = pr[t], v1 = pr[t + 256], v2 = pr[t + 512], v3 = pr[t + 768];
    __shared__ float sh[8], sh2[8], bc[2];
    float mx = fmaxf(fmaxf(v0, v1), fmaxf(v2, v3));
    for (int o = 16; o > 0; o >>= 1) mx = fmaxf(mx, __shfl_xor_sync(~0u, mx, o));
    if ((t & 31) == 0) sh[t >> 5] = mx;
    __syncthreads();
    if (t < 8) {
        float m = sh[t];
        for (int o = 4; o > 0; o >>= 1) m = fmaxf(m, __shfl_xor_sync(0xff, m, o));
        if (t == 0) bc[0] = m;
    }
    __syncthreads();
    mx = bc[0];
    v0 = __expf(v0 - mx); v1 = __expf(v1 - mx); v2 = __expf(v2 - mx); v3 = __expf(v3 - mx);
    float s = v0 + v1 + v2 + v3;
    for (int o = 16; o > 0; o >>= 1) s += __shfl_xor_sync(~0u, s, o);
    if ((t & 31) == 0) sh2[t >> 5] = s;
    __syncthreads();
    if (t < 8) {
        float m = sh2[t];
        for (int o = 4; o > 0; o >>= 1) m += __shfl_xor_sync(0xff, m, o);
        if (t == 0) bc[1] = 1.f / m;
    }
    __syncthreads();
    float inv = bc[1];
    ph[t]       = __float2half_rn(v0 * inv);
    ph[t + 256] = __float2half_rn(v1 * inv);
    ph[t + 512] = __float2half_rn(v2 * inv);
    ph[t + 768] = __float2half_rn(v3 * inv);
}

// ---------------- launch -----------------------------------------------------
#define GEMM_SMEM 65536

extern "C" void kernel_launch(void* const* d_in, const int* in_sizes, int n_in,
                              void* d_out, int out_size) {
    const float* x     = (const float*)d_in[0];
    const float* gamma = (const float*)d_in[1];
    const float* beta  = (const float*)d_in[2];
    const float* W0 = (const float*)d_in[3];  const float* b0 = (const float*)d_in[4];
    const float* W1 = (const float*)d_in[5];  const float* b1 = (const float*)d_in[6];
    const float* W2 = (const float*)d_in[7];  const float* b2 = (const float*)d_in[8];
    const float* W3 = (const float*)d_in[9];  const float* b3 = (const float*)d_in[10];
    float* out = (float*)d_out;

    void *hn, *q, *k, *v, *o, *attn, *attnh, *wt;
    cudaGetSymbolAddress(&hn, g_hn);
    cudaGetSymbolAddress(&q, g_q);
    cudaGetSymbolAddress(&k, g_k);
    cudaGetSymbolAddress(&v, g_v);
    cudaGetSymbolAddress(&o, g_o);
    cudaGetSymbolAddress(&attn, g_attn);
    cudaGetSymbolAddress(&attnh, g_attnh);
    cudaGetSymbolAddress(&wt, g_wt);

    cudaFuncSetAttribute(gemm_mma<M_SCORES>, cudaFuncAttributeMaxDynamicSharedMemorySize, GEMM_SMEM);
    cudaFuncSetAttribute(gemm_mma<M_QK>,     cudaFuncAttributeMaxDynamicSharedMemorySize, GEMM_SMEM);
    cudaFuncSetAttribute(gemm_mma<M_V>,      cudaFuncAttributeMaxDynamicSharedMemorySize, GEMM_SMEM);
    cudaFuncSetAttribute(gemm_mma<M_AV>,     cudaFuncAttributeMaxDynamicSharedMemorySize, GEMM_SMEM);
    cudaFuncSetAttribute(gemm_mma<M_FINAL>,  cudaFuncAttributeMaxDynamicSharedMemorySize, GEMM_SMEM);

    wt_kernel<<<dim3(16, 16, 4), 256>>>(W0, W1, W2, W3);
    gn_stats<<<Bsz * Gg, 256>>>(x);
    gn_apply_t<<<dim3(32, 16, Bsz), 256>>>(x, gamma, beta);

    const long long SNC = (long long)Nsp * Cch;     // 524288
    const long long SNN = (long long)Nsp * Nsp;     // 1048576
    GArgs a;

    // q[n][d] = SCALE*(hn @ W0t^T + b0)
    a = { (const __half*)hn, (const __half*)wt, q, b0, nullptr,
          SNC, 0, SNC, Cch, Cch, Cch, Cch, SCALE };
    gemm_mma<M_QK><<<dim3(4, 8, Bsz), 256, GEMM_SMEM>>>(a);
    // k[n][d]
    a = { (const __half*)hn, (const __half*)wt + (size_t)Cch * Cch, k, b1, nullptr,
          SNC, 0, SNC, Cch, Cch, Cch, Cch, 1.0f };
    gemm_mma<M_QK><<<dim3(4, 8, Bsz), 256, GEMM_SMEM>>>(a);
    // v[d][n] = W2t @ hn^T + b2[d]
    a = { (const __half*)wt + (size_t)2 * Cch * Cch, (const __half*)hn, v, b2, nullptr,
          0, SNC, SNC, Cch, Cch, Nsp, Cch, 1.0f };
    gemm_mma<M_V><<<dim3(8, 4, Bsz), 256, GEMM_SMEM>>>(a);
    // scores[i][j] = q @ k^T (fp32)
    a = { (const __half*)q, (const __half*)k, attn, nullptr, nullptr,
          SNC, SNC, SNN, Cch, Cch, Nsp, Cch, 1.0f };
    gemm_mma<M_SCORES><<<dim3(8, 8, Bsz), 256, GEMM_SMEM>>>(a);

    softmax_kernel<<<Bsz * Nsp, 256>>>();

    // o[n][c] = attn @ v^T  (K = 1024)
    a = { (const __half*)attnh, (const __half*)v, o, nullptr, nullptr,
          SNN, SNC, SNC, Nsp, Nsp, Cch, Nsp, 1.0f };
    gemm_mma<M_AV><<<dim3(4, 8, Bsz), 256, GEMM_SMEM>>>(a);
    // out[d][n] = W3t @ o^T + b3[d] + x[d][n]  (fp32)
    a = { (const __half*)wt + (size_t)3 * Cch * Cch, (const __half*)o, out, b3, x,
          0, SNC, SNC, Cch, Cch, Nsp, Cch, 1.0f };
    gemm_mma<M_FINAL><<<dim3(8, 4, Bsz), 256, GEMM_SMEM>>>(a);
}